// round 14
// baseline (speedup 1.0000x reference)
#include <cuda_runtime.h>
#include <cuda_bf16.h>
#include <mma.h>
#include <cstring>

using namespace nvcuda;

#define BB   4
#define NQ   4096
#define MKV  512
#define DIM  1152
#define NH   16
#define HD   72
#define HDP  80     // K/Q staging width (5 k-tiles)
#define HDV  96     // V/output staging width (6 col tiles)
#define QT   64     // queries per attention block

// -------- scratch (static device globals; no allocation) --------
__device__ float          g_q32  [(size_t)BB*NQ*DIM];
__device__ float          g_kv32 [(size_t)BB*MKV*2*DIM];
__device__ __nv_bfloat16  g_q16  [(size_t)BB*NQ*NH*HD];
__device__ __nv_bfloat16  g_k16  [(size_t)BB*NH*MKV*HD];
__device__ __nv_bfloat16  g_v16  [(size_t)BB*NH*MKV*HD];
__device__ __nv_bfloat16  g_att16[(size_t)BB*NQ*DIM];

// ============================================================================
// Exact FP32 GEMM (Q/KV projections). f32x2 packed FMA, double-buffered smem.
// ============================================================================
#define KC  16
#define SLD 132

__device__ __forceinline__ void fma2(unsigned long long& d,
                                     unsigned long long a,
                                     unsigned long long b)
{
    asm("fma.rn.f32x2 %0, %1, %2, %3;" : "=l"(d) : "l"(a), "l"(b), "l"(d));
}
__device__ __forceinline__ unsigned long long pack2(float x)
{
    unsigned long long r;
    asm("mov.b64 %0, {%1, %1};" : "=l"(r) : "f"(x));
    return r;
}

__global__ void __launch_bounds__(256) gemm_f32(
    const float* __restrict__ A, const float* __restrict__ B,
    const float* __restrict__ bias, float* __restrict__ C,
    int M, int N, int K)
{
    __shared__ float As[2][KC][SLD];
    __shared__ float Bs[2][KC][SLD];

    const int tid = threadIdx.x;
    const int tx  = tid & 15;
    const int ty  = tid >> 4;
    const int m0  = blockIdx.y * 128;
    const int n0  = blockIdx.x * 128;

    const int ar = tid >> 2, ac = (tid & 3) * 4;
    const int br = tid >> 5, bc = (tid & 31) * 4;

    unsigned long long acc2[8][4];
    #pragma unroll
    for (int i = 0; i < 8; ++i)
        #pragma unroll
        for (int j = 0; j < 4; ++j) acc2[i][j] = 0ull;

    const int T = K / KC;
    float4 pa0, pa1, pb0, pb1;

    pa0 = *(const float4*)&A[(size_t)(m0 + ar) * K + ac];
    pa1 = *(const float4*)&A[(size_t)(m0 + ar + 64) * K + ac];
    pb0 = *(const float4*)&B[(size_t)br * N + n0 + bc];
    pb1 = *(const float4*)&B[(size_t)(br + 8) * N + n0 + bc];
    {
        As[0][ac + 0][ar] = pa0.x; As[0][ac + 1][ar] = pa0.y;
        As[0][ac + 2][ar] = pa0.z; As[0][ac + 3][ar] = pa0.w;
        As[0][ac + 0][ar + 64] = pa1.x; As[0][ac + 1][ar + 64] = pa1.y;
        As[0][ac + 2][ar + 64] = pa1.z; As[0][ac + 3][ar + 64] = pa1.w;
        *(float4*)&Bs[0][br][bc] = pb0;
        *(float4*)&Bs[0][br + 8][bc] = pb1;
    }
    __syncthreads();

    for (int t = 0; t < T; ++t) {
        const int buf = t & 1;
        if (t + 1 < T) {
            const int kt = (t + 1) * KC;
            pa0 = *(const float4*)&A[(size_t)(m0 + ar) * K + kt + ac];
            pa1 = *(const float4*)&A[(size_t)(m0 + ar + 64) * K + kt + ac];
            pb0 = *(const float4*)&B[(size_t)(kt + br) * N + n0 + bc];
            pb1 = *(const float4*)&B[(size_t)(kt + br + 8) * N + n0 + bc];
        }

        #pragma unroll
        for (int kk = 0; kk < KC; ++kk) {
            float4 av0 = *(const float4*)&As[buf][kk][ty * 8];
            float4 av1 = *(const float4*)&As[buf][kk][ty * 8 + 4];
            float4 bv0 = *(const float4*)&Bs[buf][kk][tx * 8];
            float4 bv1 = *(const float4*)&Bs[buf][kk][tx * 8 + 4];
            unsigned long long b2[4];
            memcpy(&b2[0], &bv0, 16);
            memcpy(&b2[2], &bv1, 16);
            float a[8] = {av0.x, av0.y, av0.z, av0.w, av1.x, av1.y, av1.z, av1.w};
            #pragma unroll
            for (int i = 0; i < 8; ++i) {
                unsigned long long a2 = pack2(a[i]);
                #pragma unroll
                for (int jp = 0; jp < 4; ++jp)
                    fma2(acc2[i][jp], a2, b2[jp]);
            }
        }
        __syncthreads();

        if (t + 1 < T) {
            const int nb = buf ^ 1;
            As[nb][ac + 0][ar] = pa0.x; As[nb][ac + 1][ar] = pa0.y;
            As[nb][ac + 2][ar] = pa0.z; As[nb][ac + 3][ar] = pa0.w;
            As[nb][ac + 0][ar + 64] = pa1.x; As[nb][ac + 1][ar + 64] = pa1.y;
            As[nb][ac + 2][ar + 64] = pa1.z; As[nb][ac + 3][ar + 64] = pa1.w;
            *(float4*)&Bs[nb][br][bc] = pb0;
            *(float4*)&Bs[nb][br + 8][bc] = pb1;
            __syncthreads();
        }
    }

    #pragma unroll
    for (int i = 0; i < 8; ++i) {
        const size_t gm = m0 + ty * 8 + i;
        const int    gn = n0 + tx * 8;
        float o[8];
        memcpy(o, acc2[i], 32);
        if (bias) {
            #pragma unroll
            for (int j = 0; j < 8; ++j) o[j] += bias[gn + j];
        }
        *(float4*)&C[gm * N + gn]     = *(float4*)(o);
        *(float4*)&C[gm * N + gn + 4] = *(float4*)(o + 4);
    }
}

// ============================================================================
// Output projection: bf16x2 tensor-core GEMM (A exactly bf16; B hi/lo split).
// ============================================================================
#define OALD 40
#define OBLD 136

__global__ void __launch_bounds__(256) gemm_out_bf16(
    const __nv_bfloat16* __restrict__ A, const float* __restrict__ B,
    const float* __restrict__ bias, float* __restrict__ C,
    int M, int N, int K)
{
    __shared__ __nv_bfloat16 Asm[128 * OALD];
    __shared__ __nv_bfloat16 Bh [32 * OBLD];
    __shared__ __nv_bfloat16 Bl [32 * OBLD];

    const int tid = threadIdx.x;
    const int wid = tid >> 5;
    const int m0  = blockIdx.y * 128;
    const int n0  = blockIdx.x * 128;
    const int wr  = wid >> 1;
    const int wc  = wid & 1;

    wmma::fragment<wmma::accumulator, 16, 16, 16, float> acc[2][4];
    #pragma unroll
    for (int r = 0; r < 2; ++r)
        #pragma unroll
        for (int c = 0; c < 4; ++c)
            wmma::fill_fragment(acc[r][c], 0.0f);

    const int arow = tid >> 1, acol = (tid & 1) * 16;
    const int brow = tid >> 3, bcol = (tid & 7) * 16;

    for (int kt = 0; kt < K; kt += 32) {
        {
            const __nv_bfloat16* src = &A[(size_t)(m0 + arow) * K + kt + acol];
            *(uint4*)&Asm[arow * OALD + acol]     = *(const uint4*)src;
            *(uint4*)&Asm[arow * OALD + acol + 8] = *(const uint4*)(src + 8);
        }
        {
            const float* src = &B[(size_t)(kt + brow) * N + n0 + bcol];
            #pragma unroll
            for (int q = 0; q < 4; ++q) {
                float4 v = *(const float4*)(src + q * 4);
                #pragma unroll
                for (int e = 0; e < 4; ++e) {
                    float f = (&v.x)[e];
                    __nv_bfloat16 h = __float2bfloat16(f);
                    Bh[brow * OBLD + bcol + q * 4 + e] = h;
                    Bl[brow * OBLD + bcol + q * 4 + e] =
                        __float2bfloat16(f - __bfloat162float(h));
                }
            }
        }
        __syncthreads();

        #pragma unroll
        for (int kk = 0; kk < 32; kk += 16) {
            wmma::fragment<wmma::matrix_a, 16, 16, 16, __nv_bfloat16, wmma::row_major> af[2];
            wmma::fragment<wmma::matrix_b, 16, 16, 16, __nv_bfloat16, wmma::row_major> bhf[4], blf[4];
            #pragma unroll
            for (int r = 0; r < 2; ++r)
                wmma::load_matrix_sync(af[r], Asm + (wr * 32 + r * 16) * OALD + kk, OALD);
            #pragma unroll
            for (int c = 0; c < 4; ++c) {
                wmma::load_matrix_sync(bhf[c], Bh + kk * OBLD + wc * 64 + c * 16, OBLD);
                wmma::load_matrix_sync(blf[c], Bl + kk * OBLD + wc * 64 + c * 16, OBLD);
            }
            #pragma unroll
            for (int r = 0; r < 2; ++r)
                #pragma unroll
                for (int c = 0; c < 4; ++c) {
                    wmma::mma_sync(acc[r][c], af[r], blf[c], acc[r][c]);
                    wmma::mma_sync(acc[r][c], af[r], bhf[c], acc[r][c]);
                }
        }
        __syncthreads();
    }

    #pragma unroll
    for (int r = 0; r < 2; ++r)
        #pragma unroll
        for (int c = 0; c < 4; ++c) {
            const int gm = m0 + wr * 32 + r * 16;
            const int gn = n0 + wc * 64 + c * 16;
            float* tb = (float*)Asm + wid * 16 * 20;
            wmma::store_matrix_sync(tb, acc[r][c], 20, wmma::mem_row_major);
            __syncwarp();
            const int lane = tid & 31;
            #pragma unroll
            for (int e = lane; e < 256; e += 32) {
                int rr = e >> 4, cc = e & 15;
                C[(size_t)(gm + rr) * N + gn + cc] = tb[rr * 20 + cc] + bias[gn + cc];
            }
            __syncwarp();
        }
}

// ============================================================================
// Fused bias + RMSNorm + bf16 cast for Q and KV paths.
// ============================================================================
#define QB ((BB*NQ*NH)/8)
#define KB ((BB*MKV*NH)/8)

__global__ void __launch_bounds__(256) rms_fused(
    const float* __restrict__ q32, const float* __restrict__ qb,
    const float* __restrict__ qw, __nv_bfloat16* __restrict__ q16,
    const float* __restrict__ kv32, const float* __restrict__ kvb,
    const float* __restrict__ knw,
    __nv_bfloat16* __restrict__ k16, __nv_bfloat16* __restrict__ v16)
{
    const int wid  = threadIdx.x >> 5;
    const int lane = threadIdx.x & 31;

    if (blockIdx.x < QB) {
        const size_t row = (size_t)blockIdx.x * 8 + wid;
        const int h = (int)(row % NH);
        const float* src = q32 + row * HD;

        float v0 = src[lane]      + qb[h * HD + lane];
        float v1 = src[lane + 32] + qb[h * HD + lane + 32];
        float v2 = (lane < 8) ? src[lane + 64] + qb[h * HD + lane + 64] : 0.0f;

        float ss = v0 * v0 + v1 * v1 + v2 * v2;
        #pragma unroll
        for (int o = 16; o; o >>= 1) ss += __shfl_xor_sync(0xffffffffu, ss, o);
        const float inv = 1.0f / sqrtf(ss * (1.0f / 72.0f) + 1e-6f);

        __nv_bfloat16* dst = q16 + row * HD;
        dst[lane]      = __float2bfloat16(v0 * inv * qw[lane]);
        dst[lane + 32] = __float2bfloat16(v1 * inv * qw[lane + 32]);
        if (lane < 8)
            dst[lane + 64] = __float2bfloat16(v2 * inv * qw[lane + 64]);
    } else {
        const int rid = (blockIdx.x - QB) * 8 + wid;
        const int b = rid / (MKV * NH);
        const int m = (rid / NH) % MKV;
        const int h = rid % NH;

        const size_t base = ((size_t)(b * MKV + m) * 2) * DIM + h * HD;
        const float* ksrc = kv32 + base;
        const float* vsrc = kv32 + base + DIM;
        const float* kb   = kvb + h * HD;
        const float* vb   = kvb + DIM + h * HD;
        const size_t obase = ((size_t)(b * NH + h) * MKV + m) * HD;

        float k0 = ksrc[lane]      + kb[lane];
        float k1 = ksrc[lane + 32] + kb[lane + 32];
        float k2 = (lane < 8) ? ksrc[lane + 64] + kb[lane + 64] : 0.0f;
        float ss = k0 * k0 + k1 * k1 + k2 * k2;
        #pragma unroll
        for (int o = 16; o; o >>= 1) ss += __shfl_xor_sync(0xffffffffu, ss, o);
        const float inv = 1.0f / sqrtf(ss * (1.0f / 72.0f) + 1e-6f);
        k16[obase + lane]      = __float2bfloat16(k0 * inv * knw[lane]);
        k16[obase + lane + 32] = __float2bfloat16(k1 * inv * knw[lane + 32]);
        if (lane < 8)
            k16[obase + lane + 64] = __float2bfloat16(k2 * inv * knw[lane + 64]);

        v16[obase + lane]      = __float2bfloat16(vsrc[lane]      + vb[lane]);
        v16[obase + lane + 32] = __float2bfloat16(vsrc[lane + 32] + vb[lane + 32]);
        if (lane < 8)
            v16[obase + lane + 64] = __float2bfloat16(vsrc[lane + 64] + vb[lane + 64]);
    }
}

// ============================================================================
// Attention, QK-once variant: 512 threads (16 warps), all 4 chunk score
// buffers live in smem (QK computed ONCE), exact global softmax stats, then
// per-chunk bf16 prob conversion + PV. ~188KB smem -> 1 block/SM.
// ============================================================================
#define ATH   512
#define SCLD2 132                              // f32 score ld
#define SCSZ  (QT*SCLD2)                       // floats per chunk buffer (8448)
#define PBLD  136                              // bf16 prob ld
#define OFF_QS  0                              // [64][80] bf16  = 10240
#define OFF_KS  (OFF_QS + QT*HDP*2)            // [128][96] bf16 = 24576
#define OFF_SC  (OFF_KS + 128*HDV*2)           // 4x [64][132] f32 = 135168
#define OFF_PB  (OFF_SC + 4*SCSZ*4)            // [64][136] bf16 = 17408
#define OFF_M   (OFF_PB + QT*PBLD*2)           // 64 f32
#define OFF_S   (OFF_M + QT*4)
#define SMEM_ATTN3 (OFF_S + QT*4)              // 187904

__global__ void __launch_bounds__(ATH, 1) attn_flash(
    const __nv_bfloat16* __restrict__ q16, const __nv_bfloat16* __restrict__ k16,
    const __nv_bfloat16* __restrict__ v16, const int* __restrict__ kvlen_p,
    __nv_bfloat16* __restrict__ out)
{
    extern __shared__ char smem[];
    __nv_bfloat16* qs  = (__nv_bfloat16*)(smem + OFF_QS);
    __nv_bfloat16* ks  = (__nv_bfloat16*)(smem + OFF_KS);
    float*         sc  = (float*)(smem + OFF_SC);
    __nv_bfloat16* pb  = (__nv_bfloat16*)(smem + OFF_PB);
    float*         rowM = (float*)(smem + OFF_M);
    float*         rowS = (float*)(smem + OFF_S);

    const int tid  = threadIdx.x;
    const int wid  = tid >> 5;          // 0..15
    const int lane = tid & 31;
    const int n0 = blockIdx.x * QT;
    const int h  = blockIdx.y;
    const int b  = blockIdx.z;
    const int kvlen = kvlen_p[b];
    const int nchunks = (kvlen + 127) >> 7;
    const float scale = 0.11785113019775793f;   // 1/sqrt(72)

    // load Q tile (pad cols 72..79 with 0)
    const size_t qbase = (((size_t)(b * NQ + n0)) * NH + h) * HD;
    for (int i = tid; i < QT * HDP; i += ATH) {
        int r = i / HDP, c = i % HDP;
        qs[i] = (c < HD) ? q16[qbase + (size_t)r * NH * HD + c] : __float2bfloat16(0.0f);
    }

    const size_t kvbase = ((size_t)(b * NH + h)) * MKV * HD;
    const int rt = wid >> 2;            // 0..3 row tile (16 rows)
    const int cq = wid & 3;             // 0..3 col quarter (2 tiles)

    // ---------------- Phase 1: QK once per chunk, scores persist ----------
    for (int mc = 0; mc < nchunks; ++mc) {
        __syncthreads();
        for (int i = tid; i < 128 * HDP; i += ATH) {
            int r = i / HDP, c = i % HDP;
            ks[r * HDP + c] = (c < HD)
                ? k16[kvbase + (size_t)(mc * 128 + r) * HD + c]
                : __float2bfloat16(0.0f);
        }
        __syncthreads();
        float* scm = sc + mc * SCSZ;
        wmma::fragment<wmma::matrix_a, 16, 16, 16, __nv_bfloat16, wmma::row_major> af;
        wmma::fragment<wmma::matrix_b, 16, 16, 16, __nv_bfloat16, wmma::col_major> bf;
        #pragma unroll
        for (int cc = 0; cc < 2; ++cc) {
            const int ct = cq * 2 + cc;
            wmma::fragment<wmma::accumulator, 16, 16, 16, float> acc;
            wmma::fill_fragment(acc, 0.0f);
            #pragma unroll
            for (int kk = 0; kk < 5; ++kk) {
                wmma::load_matrix_sync(af, qs + rt * 16 * HDP + kk * 16, HDP);
                wmma::load_matrix_sync(bf, ks + ct * 16 * HDP + kk * 16, HDP);
                wmma::mma_sync(acc, af, bf, acc);
            }
            wmma::store_matrix_sync(scm + rt * 16 * SCLD2 + ct * 16, acc,
                                    SCLD2, wmma::mem_row_major);
        }
    }
    __syncthreads();

    // ---------------- Phase 2: exact stats over full rows ----------------
    #pragma unroll
    for (int t = 0; t < 4; ++t) {
        const int i = wid + 16 * t;
        float mx = -1e30f;
        for (int j = lane; j < kvlen; j += 32)
            mx = fmaxf(mx, sc[(j >> 7) * SCSZ + i * SCLD2 + (j & 127)] * scale);
        #pragma unroll
        for (int o = 16; o; o >>= 1)
            mx = fmaxf(mx, __shfl_xor_sync(0xffffffffu, mx, o));
        float sum = 0.0f;
        for (int j = lane; j < kvlen; j += 32)
            sum += __expf(sc[(j >> 7) * SCSZ + i * SCLD2 + (j & 127)] * scale - mx);
        #pragma unroll
        for (int o = 16; o; o >>= 1)
            sum += __shfl_xor_sync(0xffffffffu, sum, o);
        if (lane == 0) { rowM[i] = mx; rowS[i] = sum; }
    }
    __syncthreads();

    // ---------------- Phase 3: per-chunk probs + PV ----------------
    wmma::fragment<wmma::accumulator, 16, 16, 16, float> pvA, pvB;
    wmma::fill_fragment(pvA, 0.0f);
    wmma::fill_fragment(pvB, 0.0f);
    const int ctA = cq;                 // out col tiles 0..3
    const int ctB = 4 + cq;             // 4,5 used by cq<2
    const bool hasB = (cq < 2);

    for (int mc = 0; mc < nchunks; ++mc) {
        const float* scm = sc + mc * SCSZ;
        const int base = mc * 128;
        // probs -> pb
        #pragma unroll
        for (int t = 0; t < 4; ++t) {
            const int i = wid + 16 * t;
            const float Mi   = rowM[i];
            const float invS = 1.0f / rowS[i];
            #pragma unroll
            for (int q = 0; q < 4; ++q) {
                const int j = lane + 32 * q;
                pb[i * PBLD + j] = (base + j < kvlen)
                    ? __float2bfloat16(__expf(scm[i * SCLD2 + j] * scale - Mi) * invS)
                    : __float2bfloat16(0.0f);
            }
        }
        // V chunk -> ks as [128][96]
        for (int i = tid; i < 128 * HDV; i += ATH) {
            int r = i / HDV, c = i % HDV;
            ks[r * HDV + c] = (c < HD)
                ? v16[kvbase + (size_t)(base + r) * HD + c]
                : __float2bfloat16(0.0f);
        }
        __syncthreads();
        {
            wmma::fragment<wmma::matrix_a, 16, 16, 16, __nv_bfloat16, wmma::row_major> pf;
            wmma::fragment<wmma::matrix_b, 16, 16, 16, __nv_bfloat16, wmma::row_major> vf;
            #pragma unroll
            for (int kk = 0; kk < 8; ++kk) {
                wmma::load_matrix_sync(pf, pb + rt * 16 * PBLD + kk * 16, PBLD);
                wmma::load_matrix_sync(vf, ks + kk * 16 * HDV + ctA * 16, HDV);
                wmma::mma_sync(pvA, pf, vf, pvA);
                if (hasB) {
                    wmma::load_matrix_sync(vf, ks + kk * 16 * HDV + ctB * 16, HDV);
                    wmma::mma_sync(pvB, pf, vf, pvB);
                }
            }
        }
        __syncthreads();   // pb/ks reused next chunk
    }

    // epilogue: stage O via sc region as [64][96] f32, emit bf16
    float* os = sc;
    wmma::store_matrix_sync(os + rt * 16 * HDV + ctA * 16, pvA, HDV,
                            wmma::mem_row_major);
    if (hasB)
        wmma::store_matrix_sync(os + rt * 16 * HDV + ctB * 16, pvB, HDV,
                                wmma::mem_row_major);
    __syncthreads();
    for (int i = tid; i < QT * HD; i += ATH) {
        int r = i / HD, d = i % HD;
        out[((size_t)(b * NQ + n0 + r)) * DIM + h * HD + d] =
            __float2bfloat16(os[r * HDV + d]);
    }
}

// ============================================================================
extern "C" void kernel_launch(void* const* d_in, const int* in_sizes, int n_in,
                              void* d_out, int out_size)
{
    (void)in_sizes; (void)n_in; (void)out_size;
    const float* x      = (const float*)d_in[0];
    const float* cond   = (const float*)d_in[1];
    const int*   kvlen  = (const int*)  d_in[2];
    const float* q_w    = (const float*)d_in[3];
    const float* q_b    = (const float*)d_in[4];
    const float* kv_w   = (const float*)d_in[5];
    const float* kv_b   = (const float*)d_in[6];
    const float* proj_w = (const float*)d_in[7];
    const float* proj_b = (const float*)d_in[8];
    const float* qn_w   = (const float*)d_in[9];
    const float* kn_w   = (const float*)d_in[10];
    float* out = (float*)d_out;

    void* p;
    cudaGetSymbolAddress(&p, g_q32);   float* q32 = (float*)p;
    cudaGetSymbolAddress(&p, g_kv32);  float* kv32 = (float*)p;
    cudaGetSymbolAddress(&p, g_q16);   __nv_bfloat16* q16 = (__nv_bfloat16*)p;
    cudaGetSymbolAddress(&p, g_k16);   __nv_bfloat16* k16 = (__nv_bfloat16*)p;
    cudaGetSymbolAddress(&p, g_v16);   __nv_bfloat16* v16 = (__nv_bfloat16*)p;
    cudaGetSymbolAddress(&p, g_att16); __nv_bfloat16* att16 = (__nv_bfloat16*)p;

    cudaFuncSetAttribute(attn_flash, cudaFuncAttributeMaxDynamicSharedMemorySize,
                         SMEM_ATTN3);

    // 0) Q = x @ q_w   (exact fp32)
    gemm_f32<<<dim3(DIM / 128, (BB * NQ) / 128), 256>>>(
        x, q_w, nullptr, q32, BB * NQ, DIM, DIM);
    // 1) KV = cond @ kv_w (exact fp32)
    gemm_f32<<<dim3((2 * DIM) / 128, (BB * MKV) / 128), 256>>>(
        cond, kv_w, nullptr, kv32, BB * MKV, 2 * DIM, DIM);
    // 2) fused bias + rmsnorm + bf16
    rms_fused<<<QB + KB, 256>>>(q32, q_b, qn_w, q16, kv32, kv_b, kn_w, k16, v16);
    // 3) attention — QK once, full score residency
    attn_flash<<<dim3(NQ / QT, NH, BB), ATH, SMEM_ATTN3>>>(q16, k16, v16, kvlen, att16);
    // 4) out = att @ proj_w + proj_b — bf16x2 tensor-core
    gemm_out_bf16<<<dim3(DIM / 128, (BB * NQ) / 128), 256>>>(
        att16, proj_w, proj_b, out, BB * NQ, DIM, DIM);
}

// round 15
// speedup vs baseline: 1.0667x; 1.0667x over previous
#include <cuda_runtime.h>
#include <cuda_bf16.h>
#include <mma.h>
#include <cstring>

using namespace nvcuda;

#define BB   4
#define NQ   4096
#define MKV  512
#define DIM  1152
#define NH   16
#define HD   72
#define HDP  80     // K/Q staging width (5 k-tiles)
#define HDV  96     // V/output staging width (6 col tiles)
#define QT   64     // queries per attention block

// -------- scratch (static device globals; no allocation) --------
__device__ float          g_q32  [(size_t)BB*NQ*DIM];
__device__ float          g_kv32 [(size_t)BB*MKV*2*DIM];
__device__ __nv_bfloat16  g_q16  [(size_t)BB*NQ*NH*HD];
__device__ __nv_bfloat16  g_k16  [(size_t)BB*NH*MKV*HD];
__device__ __nv_bfloat16  g_v16  [(size_t)BB*NH*MKV*HD];
__device__ __nv_bfloat16  g_att16[(size_t)BB*NQ*DIM];

// ============================================================================
// Exact FP32 dual-GEMM (Q-proj + KV-proj in ONE launch, block-range dispatch).
// A pre-splatted to f32x2 in smem (no pack in hot loop); ascending-k fma2
// chains — bit-identical accumulation to prior rounds.
// Block tile 128x128, KC=16, per-thread 8x8.
// ============================================================================
#define KC   16
#define SLD  132
#define ALD2 130     // f32x2 lds for splatted A (pad vs 128 to stagger banks)
#define QBLK 1152    // Q-proj blocks: (16384/128) x (1152/128) = 128*9
#define KVBLK 288    // KV-proj blocks: (2048/128) x (2304/128) = 16*18

__device__ __forceinline__ void fma2(unsigned long long& d,
                                     unsigned long long a,
                                     unsigned long long b)
{
    asm("fma.rn.f32x2 %0, %1, %2, %3;" : "=l"(d) : "l"(a), "l"(b), "l"(d));
}
__device__ __forceinline__ unsigned long long splat2(float x)
{
    unsigned long long r;
    asm("mov.b64 %0, {%1, %1};" : "=l"(r) : "f"(x));
    return r;
}

__global__ void __launch_bounds__(256, 2) gemm_dual_f32(
    const float* __restrict__ xA, const float* __restrict__ qw,
    float* __restrict__ qout,
    const float* __restrict__ cA, const float* __restrict__ kvw,
    float* __restrict__ kvout)
{
    __shared__ unsigned long long As2[2][KC][ALD2];  // splatted A
    __shared__ float              Bs [2][KC][SLD];

    const float* A; const float* B; float* C;
    int N, bx, by;
    if (blockIdx.x < QBLK) {
        A = xA; B = qw; C = qout; N = DIM;
        bx = blockIdx.x % 9;  by = blockIdx.x / 9;
    } else {
        const int i = blockIdx.x - QBLK;
        A = cA; B = kvw; C = kvout; N = 2 * DIM;
        bx = i % 18; by = i / 18;
    }
    const int K = DIM;
    const int m0 = by * 128;
    const int n0 = bx * 128;

    const int tid = threadIdx.x;
    const int tx  = tid & 15;
    const int ty  = tid >> 4;
    const int ar = tid >> 2, ac = (tid & 3) * 4;
    const int br = tid >> 5, bc = (tid & 31) * 4;

    unsigned long long acc2[8][4];
    #pragma unroll
    for (int i = 0; i < 8; ++i)
        #pragma unroll
        for (int j = 0; j < 4; ++j) acc2[i][j] = 0ull;

    const int T = K / KC;
    float4 pa0, pa1, pb0, pb1;

    pa0 = *(const float4*)&A[(size_t)(m0 + ar) * K + ac];
    pa1 = *(const float4*)&A[(size_t)(m0 + ar + 64) * K + ac];
    pb0 = *(const float4*)&B[(size_t)br * N + n0 + bc];
    pb1 = *(const float4*)&B[(size_t)(br + 8) * N + n0 + bc];
    {
        #pragma unroll
        for (int e = 0; e < 4; ++e) {
            As2[0][ac + e][ar]      = splat2((&pa0.x)[e]);
            As2[0][ac + e][ar + 64] = splat2((&pa1.x)[e]);
        }
        *(float4*)&Bs[0][br][bc]     = pb0;
        *(float4*)&Bs[0][br + 8][bc] = pb1;
    }
    __syncthreads();

    for (int t = 0; t < T; ++t) {
        const int buf = t & 1;
        if (t + 1 < T) {
            const int kt = (t + 1) * KC;
            pa0 = *(const float4*)&A[(size_t)(m0 + ar) * K + kt + ac];
            pa1 = *(const float4*)&A[(size_t)(m0 + ar + 64) * K + kt + ac];
            pb0 = *(const float4*)&B[(size_t)(kt + br) * N + n0 + bc];
            pb1 = *(const float4*)&B[(size_t)(kt + br + 8) * N + n0 + bc];
        }

        #pragma unroll
        for (int kk = 0; kk < KC; ++kk) {
            unsigned long long a2[8], b2[4];
            *(uint4*)&a2[0] = *(const uint4*)&As2[buf][kk][ty * 8];
            *(uint4*)&a2[2] = *(const uint4*)&As2[buf][kk][ty * 8 + 2];
            *(uint4*)&a2[4] = *(const uint4*)&As2[buf][kk][ty * 8 + 4];
            *(uint4*)&a2[6] = *(const uint4*)&As2[buf][kk][ty * 8 + 6];
            float4 bv0 = *(const float4*)&Bs[buf][kk][tx * 8];
            float4 bv1 = *(const float4*)&Bs[buf][kk][tx * 8 + 4];
            memcpy(&b2[0], &bv0, 16);
            memcpy(&b2[2], &bv1, 16);
            #pragma unroll
            for (int i = 0; i < 8; ++i)
                #pragma unroll
                for (int jp = 0; jp < 4; ++jp)
                    fma2(acc2[i][jp], a2[i], b2[jp]);
        }
        __syncthreads();

        if (t + 1 < T) {
            const int nb = buf ^ 1;
            #pragma unroll
            for (int e = 0; e < 4; ++e) {
                As2[nb][ac + e][ar]      = splat2((&pa0.x)[e]);
                As2[nb][ac + e][ar + 64] = splat2((&pa1.x)[e]);
            }
            *(float4*)&Bs[nb][br][bc]     = pb0;
            *(float4*)&Bs[nb][br + 8][bc] = pb1;
            __syncthreads();
        }
    }

    #pragma unroll
    for (int i = 0; i < 8; ++i) {
        const size_t gm = m0 + ty * 8 + i;
        const int    gn = n0 + tx * 8;
        float o[8];
        memcpy(o, acc2[i], 32);
        *(float4*)&C[gm * N + gn]     = *(float4*)(o);
        *(float4*)&C[gm * N + gn + 4] = *(float4*)(o + 4);
    }
}

// ============================================================================
// Output projection: bf16x2 tensor-core GEMM (A exactly bf16; B hi/lo split).
// ============================================================================
#define OALD 40
#define OBLD 136

__global__ void __launch_bounds__(256) gemm_out_bf16(
    const __nv_bfloat16* __restrict__ A, const float* __restrict__ B,
    const float* __restrict__ bias, float* __restrict__ C,
    int M, int N, int K)
{
    __shared__ __nv_bfloat16 Asm[128 * OALD];
    __shared__ __nv_bfloat16 Bh [32 * OBLD];
    __shared__ __nv_bfloat16 Bl [32 * OBLD];

    const int tid = threadIdx.x;
    const int wid = tid >> 5;
    const int m0  = blockIdx.y * 128;
    const int n0  = blockIdx.x * 128;
    const int wr  = wid >> 1;
    const int wc  = wid & 1;

    wmma::fragment<wmma::accumulator, 16, 16, 16, float> acc[2][4];
    #pragma unroll
    for (int r = 0; r < 2; ++r)
        #pragma unroll
        for (int c = 0; c < 4; ++c)
            wmma::fill_fragment(acc[r][c], 0.0f);

    const int arow = tid >> 1, acol = (tid & 1) * 16;
    const int brow = tid >> 3, bcol = (tid & 7) * 16;

    for (int kt = 0; kt < K; kt += 32) {
        {
            const __nv_bfloat16* src = &A[(size_t)(m0 + arow) * K + kt + acol];
            *(uint4*)&Asm[arow * OALD + acol]     = *(const uint4*)src;
            *(uint4*)&Asm[arow * OALD + acol + 8] = *(const uint4*)(src + 8);
        }
        {
            const float* src = &B[(size_t)(kt + brow) * N + n0 + bcol];
            #pragma unroll
            for (int q = 0; q < 4; ++q) {
                float4 v = *(const float4*)(src + q * 4);
                #pragma unroll
                for (int e = 0; e < 4; ++e) {
                    float f = (&v.x)[e];
                    __nv_bfloat16 h = __float2bfloat16(f);
                    Bh[brow * OBLD + bcol + q * 4 + e] = h;
                    Bl[brow * OBLD + bcol + q * 4 + e] =
                        __float2bfloat16(f - __bfloat162float(h));
                }
            }
        }
        __syncthreads();

        #pragma unroll
        for (int kk = 0; kk < 32; kk += 16) {
            wmma::fragment<wmma::matrix_a, 16, 16, 16, __nv_bfloat16, wmma::row_major> af[2];
            wmma::fragment<wmma::matrix_b, 16, 16, 16, __nv_bfloat16, wmma::row_major> bhf[4], blf[4];
            #pragma unroll
            for (int r = 0; r < 2; ++r)
                wmma::load_matrix_sync(af[r], Asm + (wr * 32 + r * 16) * OALD + kk, OALD);
            #pragma unroll
            for (int c = 0; c < 4; ++c) {
                wmma::load_matrix_sync(bhf[c], Bh + kk * OBLD + wc * 64 + c * 16, OBLD);
                wmma::load_matrix_sync(blf[c], Bl + kk * OBLD + wc * 64 + c * 16, OBLD);
            }
            #pragma unroll
            for (int r = 0; r < 2; ++r)
                #pragma unroll
                for (int c = 0; c < 4; ++c) {
                    wmma::mma_sync(acc[r][c], af[r], blf[c], acc[r][c]);
                    wmma::mma_sync(acc[r][c], af[r], bhf[c], acc[r][c]);
                }
        }
        __syncthreads();
    }

    #pragma unroll
    for (int r = 0; r < 2; ++r)
        #pragma unroll
        for (int c = 0; c < 4; ++c) {
            const int gm = m0 + wr * 32 + r * 16;
            const int gn = n0 + wc * 64 + c * 16;
            float* tb = (float*)Asm + wid * 16 * 20;
            wmma::store_matrix_sync(tb, acc[r][c], 20, wmma::mem_row_major);
            __syncwarp();
            const int lane = tid & 31;
            #pragma unroll
            for (int e = lane; e < 256; e += 32) {
                int rr = e >> 4, cc = e & 15;
                C[(size_t)(gm + rr) * N + gn + cc] = tb[rr * 20 + cc] + bias[gn + cc];
            }
            __syncwarp();
        }
}

// ============================================================================
// Fused bias + RMSNorm + bf16 cast for Q and KV paths.
// ============================================================================
#define QB ((BB*NQ*NH)/8)
#define KB ((BB*MKV*NH)/8)

__global__ void __launch_bounds__(256) rms_fused(
    const float* __restrict__ q32, const float* __restrict__ qb,
    const float* __restrict__ qw, __nv_bfloat16* __restrict__ q16,
    const float* __restrict__ kv32, const float* __restrict__ kvb,
    const float* __restrict__ knw,
    __nv_bfloat16* __restrict__ k16, __nv_bfloat16* __restrict__ v16)
{
    const int wid  = threadIdx.x >> 5;
    const int lane = threadIdx.x & 31;

    if (blockIdx.x < QB) {
        const size_t row = (size_t)blockIdx.x * 8 + wid;
        const int h = (int)(row % NH);
        const float* src = q32 + row * HD;

        float v0 = src[lane]      + qb[h * HD + lane];
        float v1 = src[lane + 32] + qb[h * HD + lane + 32];
        float v2 = (lane < 8) ? src[lane + 64] + qb[h * HD + lane + 64] : 0.0f;

        float ss = v0 * v0 + v1 * v1 + v2 * v2;
        #pragma unroll
        for (int o = 16; o; o >>= 1) ss += __shfl_xor_sync(0xffffffffu, ss, o);
        const float inv = 1.0f / sqrtf(ss * (1.0f / 72.0f) + 1e-6f);

        __nv_bfloat16* dst = q16 + row * HD;
        dst[lane]      = __float2bfloat16(v0 * inv * qw[lane]);
        dst[lane + 32] = __float2bfloat16(v1 * inv * qw[lane + 32]);
        if (lane < 8)
            dst[lane + 64] = __float2bfloat16(v2 * inv * qw[lane + 64]);
    } else {
        const int rid = (blockIdx.x - QB) * 8 + wid;
        const int b = rid / (MKV * NH);
        const int m = (rid / NH) % MKV;
        const int h = rid % NH;

        const size_t base = ((size_t)(b * MKV + m) * 2) * DIM + h * HD;
        const float* ksrc = kv32 + base;
        const float* vsrc = kv32 + base + DIM;
        const float* kb   = kvb + h * HD;
        const float* vb   = kvb + DIM + h * HD;
        const size_t obase = ((size_t)(b * NH + h) * MKV + m) * HD;

        float k0 = ksrc[lane]      + kb[lane];
        float k1 = ksrc[lane + 32] + kb[lane + 32];
        float k2 = (lane < 8) ? ksrc[lane + 64] + kb[lane + 64] : 0.0f;
        float ss = k0 * k0 + k1 * k1 + k2 * k2;
        #pragma unroll
        for (int o = 16; o; o >>= 1) ss += __shfl_xor_sync(0xffffffffu, ss, o);
        const float inv = 1.0f / sqrtf(ss * (1.0f / 72.0f) + 1e-6f);
        k16[obase + lane]      = __float2bfloat16(k0 * inv * knw[lane]);
        k16[obase + lane + 32] = __float2bfloat16(k1 * inv * knw[lane + 32]);
        if (lane < 8)
            k16[obase + lane + 64] = __float2bfloat16(k2 * inv * knw[lane + 64]);

        v16[obase + lane]      = __float2bfloat16(vsrc[lane]      + vb[lane]);
        v16[obase + lane + 32] = __float2bfloat16(vsrc[lane + 32] + vb[lane + 32]);
        if (lane < 8)
            v16[obase + lane + 64] = __float2bfloat16(vsrc[lane + 64] + vb[lane + 64]);
    }
}

// ============================================================================
// Two-pass online-softmax attention — R13 best configuration, verbatim.
// QT=64, 69KB smem -> 3 blocks/SM, aliased prob buffer, __expf.
// ============================================================================
#define SCLD 132
#define PBLD 136
#define OFF_QS  0
#define OFF_KS  (OFF_QS + QT*HDP*2)            // 10240
#define OFF_SC  (OFF_KS + 128*HDV*2)           // 34816
#define OFF_M   (OFF_SC + QT*SCLD*4)           // 68608
#define OFF_S   (OFF_M + QT*4)                 // 68864
#define SMEM_ATTN2 (OFF_S + QT*4)              // 69120

__global__ void __launch_bounds__(256, 3) attn_flash(
    const __nv_bfloat16* __restrict__ q16, const __nv_bfloat16* __restrict__ k16,
    const __nv_bfloat16* __restrict__ v16, const int* __restrict__ kvlen_p,
    __nv_bfloat16* __restrict__ out)
{
    extern __shared__ char smem[];
    __nv_bfloat16* qs  = (__nv_bfloat16*)(smem + OFF_QS);
    __nv_bfloat16* ks  = (__nv_bfloat16*)(smem + OFF_KS);
    float*         sc  = (float*)(smem + OFF_SC);
    __nv_bfloat16* pb  = (__nv_bfloat16*)(smem + OFF_SC);   // ALIASED
    float*         rowM = (float*)(smem + OFF_M);
    float*         rowS = (float*)(smem + OFF_S);

    const int tid  = threadIdx.x;
    const int wid  = tid >> 5;
    const int lane = tid & 31;
    const int n0 = blockIdx.x * QT;
    const int h  = blockIdx.y;
    const int b  = blockIdx.z;
    const int kvlen = kvlen_p[b];
    const int nchunks = (kvlen + 127) >> 7;
    const float scale = 0.11785113019775793f;

    const size_t qbase = (((size_t)(b * NQ + n0)) * NH + h) * HD;
    for (int i = tid; i < QT * HDP; i += 256) {
        int r = i / HDP, c = i % HDP;
        qs[i] = (c < HD) ? q16[qbase + (size_t)r * NH * HD + c] : __float2bfloat16(0.0f);
    }
    if (tid < QT) { rowM[tid] = -1e30f; rowS[tid] = 0.0f; }

    const size_t kvbase = ((size_t)(b * NH + h)) * MKV * HD;
    const int rt = wid >> 1;
    const int ch = wid & 1;

    // Pass A: online stats
    for (int mc = 0; mc < nchunks; ++mc) {
        __syncthreads();
        for (int i = tid; i < 128 * HDP; i += 256) {
            int r = i / HDP, c = i % HDP;
            ks[r * HDP + c] = (c < HD)
                ? k16[kvbase + (size_t)(mc * 128 + r) * HD + c]
                : __float2bfloat16(0.0f);
        }
        __syncthreads();
        {
            wmma::fragment<wmma::matrix_a, 16, 16, 16, __nv_bfloat16, wmma::row_major> af;
            wmma::fragment<wmma::matrix_b, 16, 16, 16, __nv_bfloat16, wmma::col_major> bf;
            #pragma unroll
            for (int cc = 0; cc < 4; ++cc) {
                const int ct = ch * 4 + cc;
                wmma::fragment<wmma::accumulator, 16, 16, 16, float> acc;
                wmma::fill_fragment(acc, 0.0f);
                #pragma unroll
                for (int kk = 0; kk < 5; ++kk) {
                    wmma::load_matrix_sync(af, qs + rt * 16 * HDP + kk * 16, HDP);
                    wmma::load_matrix_sync(bf, ks + ct * 16 * HDP + kk * 16, HDP);
                    wmma::mma_sync(acc, af, bf, acc);
                }
                wmma::store_matrix_sync(sc + rt * 16 * SCLD + ct * 16, acc,
                                        SCLD, wmma::mem_row_major);
            }
        }
        __syncthreads();
        const int vmax = min(128, kvlen - mc * 128);
        for (int i = wid; i < QT; i += 8) {
            float* row = sc + i * SCLD;
            float cmax = -1e30f;
            for (int j = lane; j < vmax; j += 32)
                cmax = fmaxf(cmax, row[j] * scale);
            #pragma unroll
            for (int o = 16; o; o >>= 1)
                cmax = fmaxf(cmax, __shfl_xor_sync(0xffffffffu, cmax, o));
            const float m_old = rowM[i];
            const float m_new = fmaxf(m_old, cmax);
            float csum = 0.0f;
            for (int j = lane; j < vmax; j += 32)
                csum += __expf(row[j] * scale - m_new);
            #pragma unroll
            for (int o = 16; o; o >>= 1)
                csum += __shfl_xor_sync(0xffffffffu, csum, o);
            if (lane == 0) {
                rowS[i] = rowS[i] * __expf(m_old - m_new) + csum;
                rowM[i] = m_new;
            }
        }
    }
    __syncthreads();

    // Pass B: probs + PV
    wmma::fragment<wmma::accumulator, 16, 16, 16, float> pv[3];
    #pragma unroll
    for (int c3 = 0; c3 < 3; ++c3)
        wmma::fill_fragment(pv[c3], 0.0f);

    for (int mc = 0; mc < nchunks; ++mc) {
        for (int i = tid; i < 128 * HDP; i += 256) {
            int r = i / HDP, c = i % HDP;
            ks[r * HDP + c] = (c < HD)
                ? k16[kvbase + (size_t)(mc * 128 + r) * HD + c]
                : __float2bfloat16(0.0f);
        }
        __syncthreads();
        {
            wmma::fragment<wmma::matrix_a, 16, 16, 16, __nv_bfloat16, wmma::row_major> af;
            wmma::fragment<wmma::matrix_b, 16, 16, 16, __nv_bfloat16, wmma::col_major> bf;
            #pragma unroll
            for (int cc = 0; cc < 4; ++cc) {
                const int ct = ch * 4 + cc;
                wmma::fragment<wmma::accumulator, 16, 16, 16, float> acc;
                wmma::fill_fragment(acc, 0.0f);
                #pragma unroll
                for (int kk = 0; kk < 5; ++kk) {
                    wmma::load_matrix_sync(af, qs + rt * 16 * HDP + kk * 16, HDP);
                    wmma::load_matrix_sync(bf, ks + ct * 16 * HDP + kk * 16, HDP);
                    wmma::mma_sync(acc, af, bf, acc);
                }
                wmma::store_matrix_sync(sc + rt * 16 * SCLD + ct * 16, acc,
                                        SCLD, wmma::mem_row_major);
            }
        }
        __syncthreads();
        const int vmax = min(128, kvlen - mc * 128);
        float preg[8][4];
        #pragma unroll
        for (int t = 0; t < 8; ++t) {
            const int i = wid + 8 * t;
            const float Mi   = rowM[i];
            const float invS = 1.0f / rowS[i];
            const float* row = sc + i * SCLD;
            #pragma unroll
            for (int q = 0; q < 4; ++q) {
                const int j = lane + 32 * q;
                preg[t][q] = (j < vmax) ? __expf(row[j] * scale - Mi) * invS : 0.0f;
            }
        }
        __syncthreads();
        #pragma unroll
        for (int t = 0; t < 8; ++t) {
            const int i = wid + 8 * t;
            __nv_bfloat16* prow = pb + i * PBLD;
            #pragma unroll
            for (int q = 0; q < 4; ++q)
                prow[lane + 32 * q] = __float2bfloat16(preg[t][q]);
        }
        for (int i = tid; i < 128 * HDV; i += 256) {
            int r = i / HDV, c = i % HDV;
            ks[r * HDV + c] = (c < HD)
                ? v16[kvbase + (size_t)(mc * 128 + r) * HD + c]
                : __float2bfloat16(0.0f);
        }
        __syncthreads();
        {
            wmma::fragment<wmma::matrix_a, 16, 16, 16, __nv_bfloat16, wmma::row_major> pf;
            wmma::fragment<wmma::matrix_b, 16, 16, 16, __nv_bfloat16, wmma::row_major> vf;
            #pragma unroll
            for (int kk = 0; kk < 8; ++kk) {
                wmma::load_matrix_sync(pf, pb + rt * 16 * PBLD + kk * 16, PBLD);
                #pragma unroll
                for (int c3 = 0; c3 < 3; ++c3) {
                    wmma::load_matrix_sync(vf, ks + kk * 16 * HDV + (ch * 3 + c3) * 16, HDV);
                    wmma::mma_sync(pv[c3], pf, vf, pv[c3]);
                }
            }
        }
        __syncthreads();
    }

    float* os = sc;
    #pragma unroll
    for (int c3 = 0; c3 < 3; ++c3)
        wmma::store_matrix_sync(os + rt * 16 * HDV + (ch * 3 + c3) * 16, pv[c3],
                                HDV, wmma::mem_row_major);
    __syncthreads();
    for (int i = tid; i < QT * HD; i += 256) {
        int r = i / HD, d = i % HD;
        out[((size_t)(b * NQ + n0 + r)) * DIM + h * HD + d] =
            __float2bfloat16(os[r * HDV + d]);
    }
}

// ============================================================================
extern "C" void kernel_launch(void* const* d_in, const int* in_sizes, int n_in,
                              void* d_out, int out_size)
{
    (void)in_sizes; (void)n_in; (void)out_size;
    const float* x      = (const float*)d_in[0];
    const float* cond   = (const float*)d_in[1];
    const int*   kvlen  = (const int*)  d_in[2];
    const float* q_w    = (const float*)d_in[3];
    const float* q_b    = (const float*)d_in[4];
    const float* kv_w   = (const float*)d_in[5];
    const float* kv_b   = (const float*)d_in[6];
    const float* proj_w = (const float*)d_in[7];
    const float* proj_b = (const float*)d_in[8];
    const float* qn_w   = (const float*)d_in[9];
    const float* kn_w   = (const float*)d_in[10];
    float* out = (float*)d_out;

    void* p;
    cudaGetSymbolAddress(&p, g_q32);   float* q32 = (float*)p;
    cudaGetSymbolAddress(&p, g_kv32);  float* kv32 = (float*)p;
    cudaGetSymbolAddress(&p, g_q16);   __nv_bfloat16* q16 = (__nv_bfloat16*)p;
    cudaGetSymbolAddress(&p, g_k16);   __nv_bfloat16* k16 = (__nv_bfloat16*)p;
    cudaGetSymbolAddress(&p, g_v16);   __nv_bfloat16* v16 = (__nv_bfloat16*)p;
    cudaGetSymbolAddress(&p, g_att16); __nv_bfloat16* att16 = (__nv_bfloat16*)p;

    cudaFuncSetAttribute(attn_flash, cudaFuncAttributeMaxDynamicSharedMemorySize,
                         SMEM_ATTN2);

    // 0) Q = x @ q_w AND KV = cond @ kv_w in one launch (exact fp32)
    gemm_dual_f32<<<QBLK + KVBLK, 256>>>(x, q_w, q32, cond, kv_w, kv32);
    // 1) fused bias + rmsnorm + bf16
    rms_fused<<<QB + KB, 256>>>(q32, q_b, qn_w, q16, kv32, kv_b, kn_w, k16, v16);
    // 2) attention — R13 best config
    attn_flash<<<dim3(NQ / QT, NH, BB), 256, SMEM_ATTN2>>>(q16, k16, v16, kvlen, att16);
    // 3) out = att @ proj_w + proj_b — bf16x2 tensor-core
    gemm_out_bf16<<<dim3(DIM / 128, (BB * NQ) / 128), 256>>>(
        att16, proj_w, proj_b, out, BB * NQ, DIM, DIM);
}

// round 16
// speedup vs baseline: 1.1218x; 1.0516x over previous
#include <cuda_runtime.h>
#include <cuda_bf16.h>
#include <mma.h>
#include <cstring>

using namespace nvcuda;

#define BB   4
#define NQ   4096
#define MKV  512
#define DIM  1152
#define NH   16
#define HD   72
#define HDP  80     // K/Q staging width (5 k-tiles)
#define HDV  96     // V/output staging width (6 col tiles)
#define QT   64     // queries per attention block
#define MFIX 9.0f   // fixed softmax shift: |s*scale| <= sqrt(72)*1.008 < 9

// -------- scratch (static device globals; no allocation) --------
__device__ float          g_q32  [(size_t)BB*NQ*DIM];
__device__ float          g_kv32 [(size_t)BB*MKV*2*DIM];
__device__ __nv_bfloat16  g_q16  [(size_t)BB*NQ*NH*HD];
__device__ __nv_bfloat16  g_k16  [(size_t)BB*NH*MKV*HD];
__device__ __nv_bfloat16  g_v16  [(size_t)BB*NH*MKV*HD];
__device__ __nv_bfloat16  g_att16[(size_t)BB*NQ*DIM];
__device__ __nv_bfloat16  g_pwh  [(size_t)DIM*DIM];   // proj_w hi (bf16 RNE)
__device__ __nv_bfloat16  g_pwl  [(size_t)DIM*DIM];   // proj_w lo

// ============================================================================
// Exact FP32 dual-GEMM (Q-proj + KV-proj, one launch). R13 inner loop:
// f32 A in smem, pack2 in registers, ascending-k fma2 chains (bit-identical).
// ============================================================================
#define KC   16
#define SLD  132
#define QBLK 1152    // (16384/128) x (1152/128)
#define KVBLK 288    // (2048/128) x (2304/128)

__device__ __forceinline__ void fma2(unsigned long long& d,
                                     unsigned long long a,
                                     unsigned long long b)
{
    asm("fma.rn.f32x2 %0, %1, %2, %3;" : "=l"(d) : "l"(a), "l"(b), "l"(d));
}
__device__ __forceinline__ unsigned long long pack2(float x)
{
    unsigned long long r;
    asm("mov.b64 %0, {%1, %1};" : "=l"(r) : "f"(x));
    return r;
}

__global__ void __launch_bounds__(256) gemm_dual_f32(
    const float* __restrict__ xA, const float* __restrict__ qw,
    float* __restrict__ qout,
    const float* __restrict__ cA, const float* __restrict__ kvw,
    float* __restrict__ kvout)
{
    __shared__ float As[2][KC][SLD];
    __shared__ float Bs[2][KC][SLD];

    const float* A; const float* B; float* C;
    int N, bx, by;
    if (blockIdx.x < QBLK) {
        A = xA; B = qw; C = qout; N = DIM;
        bx = blockIdx.x % 9;  by = blockIdx.x / 9;
    } else {
        const int i = blockIdx.x - QBLK;
        A = cA; B = kvw; C = kvout; N = 2 * DIM;
        bx = i % 18; by = i / 18;
    }
    const int K = DIM;
    const int m0 = by * 128;
    const int n0 = bx * 128;

    const int tid = threadIdx.x;
    const int tx  = tid & 15;
    const int ty  = tid >> 4;
    const int ar = tid >> 2, ac = (tid & 3) * 4;
    const int br = tid >> 5, bc = (tid & 31) * 4;

    unsigned long long acc2[8][4];
    #pragma unroll
    for (int i = 0; i < 8; ++i)
        #pragma unroll
        for (int j = 0; j < 4; ++j) acc2[i][j] = 0ull;

    const int T = K / KC;
    float4 pa0, pa1, pb0, pb1;

    pa0 = *(const float4*)&A[(size_t)(m0 + ar) * K + ac];
    pa1 = *(const float4*)&A[(size_t)(m0 + ar + 64) * K + ac];
    pb0 = *(const float4*)&B[(size_t)br * N + n0 + bc];
    pb1 = *(const float4*)&B[(size_t)(br + 8) * N + n0 + bc];
    {
        As[0][ac + 0][ar] = pa0.x; As[0][ac + 1][ar] = pa0.y;
        As[0][ac + 2][ar] = pa0.z; As[0][ac + 3][ar] = pa0.w;
        As[0][ac + 0][ar + 64] = pa1.x; As[0][ac + 1][ar + 64] = pa1.y;
        As[0][ac + 2][ar + 64] = pa1.z; As[0][ac + 3][ar + 64] = pa1.w;
        *(float4*)&Bs[0][br][bc]     = pb0;
        *(float4*)&Bs[0][br + 8][bc] = pb1;
    }
    __syncthreads();

    for (int t = 0; t < T; ++t) {
        const int buf = t & 1;
        if (t + 1 < T) {
            const int kt = (t + 1) * KC;
            pa0 = *(const float4*)&A[(size_t)(m0 + ar) * K + kt + ac];
            pa1 = *(const float4*)&A[(size_t)(m0 + ar + 64) * K + kt + ac];
            pb0 = *(const float4*)&B[(size_t)(kt + br) * N + n0 + bc];
            pb1 = *(const float4*)&B[(size_t)(kt + br + 8) * N + n0 + bc];
        }

        #pragma unroll
        for (int kk = 0; kk < KC; ++kk) {
            float4 av0 = *(const float4*)&As[buf][kk][ty * 8];
            float4 av1 = *(const float4*)&As[buf][kk][ty * 8 + 4];
            float4 bv0 = *(const float4*)&Bs[buf][kk][tx * 8];
            float4 bv1 = *(const float4*)&Bs[buf][kk][tx * 8 + 4];
            unsigned long long b2[4];
            memcpy(&b2[0], &bv0, 16);
            memcpy(&b2[2], &bv1, 16);
            float a[8] = {av0.x, av0.y, av0.z, av0.w, av1.x, av1.y, av1.z, av1.w};
            #pragma unroll
            for (int i = 0; i < 8; ++i) {
                unsigned long long a2 = pack2(a[i]);
                #pragma unroll
                for (int jp = 0; jp < 4; ++jp)
                    fma2(acc2[i][jp], a2, b2[jp]);
            }
        }
        __syncthreads();

        if (t + 1 < T) {
            const int nb = buf ^ 1;
            As[nb][ac + 0][ar] = pa0.x; As[nb][ac + 1][ar] = pa0.y;
            As[nb][ac + 2][ar] = pa0.z; As[nb][ac + 3][ar] = pa0.w;
            As[nb][ac + 0][ar + 64] = pa1.x; As[nb][ac + 1][ar + 64] = pa1.y;
            As[nb][ac + 2][ar + 64] = pa1.z; As[nb][ac + 3][ar + 64] = pa1.w;
            *(float4*)&Bs[nb][br][bc]     = pb0;
            *(float4*)&Bs[nb][br + 8][bc] = pb1;
            __syncthreads();
        }
    }

    #pragma unroll
    for (int i = 0; i < 8; ++i) {
        const size_t gm = m0 + ty * 8 + i;
        const int    gn = n0 + tx * 8;
        float o[8];
        memcpy(o, acc2[i], 32);
        *(float4*)&C[gm * N + gn]     = *(float4*)(o);
        *(float4*)&C[gm * N + gn + 4] = *(float4*)(o + 4);
    }
}

// ============================================================================
// Pre-split proj_w into bf16 hi/lo (identical values to prior in-GEMM split).
// ============================================================================
__global__ void __launch_bounds__(256) split_w_kernel(
    const float* __restrict__ w,
    __nv_bfloat16* __restrict__ wh, __nv_bfloat16* __restrict__ wl)
{
    const size_t i4 = ((size_t)blockIdx.x * 256 + threadIdx.x) * 4;
    float4 v = *(const float4*)&w[i4];
    #pragma unroll
    for (int e = 0; e < 4; ++e) {
        float f = (&v.x)[e];
        __nv_bfloat16 h = __float2bfloat16(f);
        wh[i4 + e] = h;
        wl[i4 + e] = __float2bfloat16(f - __bfloat162float(h));
    }
}

// ============================================================================
// Output projection: bf16x2 tensor-core GEMM, B pre-split in global.
// ============================================================================
#define OALD 40
#define OBLD 136

__global__ void __launch_bounds__(256) gemm_out_bf16(
    const __nv_bfloat16* __restrict__ A,
    const __nv_bfloat16* __restrict__ Bhg, const __nv_bfloat16* __restrict__ Blg,
    const float* __restrict__ bias, float* __restrict__ C,
    int M, int N, int K)
{
    __shared__ __nv_bfloat16 Asm[128 * OALD];
    __shared__ __nv_bfloat16 Bh [32 * OBLD];
    __shared__ __nv_bfloat16 Bl [32 * OBLD];

    const int tid = threadIdx.x;
    const int wid = tid >> 5;
    const int m0  = blockIdx.y * 128;
    const int n0  = blockIdx.x * 128;
    const int wr  = wid >> 1;
    const int wc  = wid & 1;

    wmma::fragment<wmma::accumulator, 16, 16, 16, float> acc[2][4];
    #pragma unroll
    for (int r = 0; r < 2; ++r)
        #pragma unroll
        for (int c = 0; c < 4; ++c)
            wmma::fill_fragment(acc[r][c], 0.0f);

    const int arow = tid >> 1, acol = (tid & 1) * 16;
    const int brow = tid >> 3, bcol = (tid & 7) * 16;

    for (int kt = 0; kt < K; kt += 32) {
        {
            const __nv_bfloat16* src = &A[(size_t)(m0 + arow) * K + kt + acol];
            *(uint4*)&Asm[arow * OALD + acol]     = *(const uint4*)src;
            *(uint4*)&Asm[arow * OALD + acol + 8] = *(const uint4*)(src + 8);
        }
        {
            const size_t goff = (size_t)(kt + brow) * N + n0 + bcol;
            *(uint4*)&Bh[brow * OBLD + bcol]     = *(const uint4*)&Bhg[goff];
            *(uint4*)&Bh[brow * OBLD + bcol + 8] = *(const uint4*)&Bhg[goff + 8];
            *(uint4*)&Bl[brow * OBLD + bcol]     = *(const uint4*)&Blg[goff];
            *(uint4*)&Bl[brow * OBLD + bcol + 8] = *(const uint4*)&Blg[goff + 8];
        }
        __syncthreads();

        #pragma unroll
        for (int kk = 0; kk < 32; kk += 16) {
            wmma::fragment<wmma::matrix_a, 16, 16, 16, __nv_bfloat16, wmma::row_major> af[2];
            wmma::fragment<wmma::matrix_b, 16, 16, 16, __nv_bfloat16, wmma::row_major> bhf[4], blf[4];
            #pragma unroll
            for (int r = 0; r < 2; ++r)
                wmma::load_matrix_sync(af[r], Asm + (wr * 32 + r * 16) * OALD + kk, OALD);
            #pragma unroll
            for (int c = 0; c < 4; ++c) {
                wmma::load_matrix_sync(bhf[c], Bh + kk * OBLD + wc * 64 + c * 16, OBLD);
                wmma::load_matrix_sync(blf[c], Bl + kk * OBLD + wc * 64 + c * 16, OBLD);
            }
            #pragma unroll
            for (int r = 0; r < 2; ++r)
                #pragma unroll
                for (int c = 0; c < 4; ++c) {
                    wmma::mma_sync(acc[r][c], af[r], blf[c], acc[r][c]);
                    wmma::mma_sync(acc[r][c], af[r], bhf[c], acc[r][c]);
                }
        }
        __syncthreads();
    }

    #pragma unroll
    for (int r = 0; r < 2; ++r)
        #pragma unroll
        for (int c = 0; c < 4; ++c) {
            const int gm = m0 + wr * 32 + r * 16;
            const int gn = n0 + wc * 64 + c * 16;
            float* tb = (float*)Asm + wid * 16 * 20;
            wmma::store_matrix_sync(tb, acc[r][c], 20, wmma::mem_row_major);
            __syncwarp();
            const int lane = tid & 31;
            #pragma unroll
            for (int e = lane; e < 256; e += 32) {
                int rr = e >> 4, cc = e & 15;
                C[(size_t)(gm + rr) * N + gn + cc] = tb[rr * 20 + cc] + bias[gn + cc];
            }
            __syncwarp();
        }
}

// ============================================================================
// Fused bias + RMSNorm + bf16 cast for Q and KV paths.
// ============================================================================
#define QB ((BB*NQ*NH)/8)
#define KB ((BB*MKV*NH)/8)

__global__ void __launch_bounds__(256) rms_fused(
    const float* __restrict__ q32, const float* __restrict__ qb,
    const float* __restrict__ qw, __nv_bfloat16* __restrict__ q16,
    const float* __restrict__ kv32, const float* __restrict__ kvb,
    const float* __restrict__ knw,
    __nv_bfloat16* __restrict__ k16, __nv_bfloat16* __restrict__ v16)
{
    const int wid  = threadIdx.x >> 5;
    const int lane = threadIdx.x & 31;

    if (blockIdx.x < QB) {
        const size_t row = (size_t)blockIdx.x * 8 + wid;
        const int h = (int)(row % NH);
        const float* src = q32 + row * HD;

        float v0 = src[lane]      + qb[h * HD + lane];
        float v1 = src[lane + 32] + qb[h * HD + lane + 32];
        float v2 = (lane < 8) ? src[lane + 64] + qb[h * HD + lane + 64] : 0.0f;

        float ss = v0 * v0 + v1 * v1 + v2 * v2;
        #pragma unroll
        for (int o = 16; o; o >>= 1) ss += __shfl_xor_sync(0xffffffffu, ss, o);
        const float inv = 1.0f / sqrtf(ss * (1.0f / 72.0f) + 1e-6f);

        __nv_bfloat16* dst = q16 + row * HD;
        dst[lane]      = __float2bfloat16(v0 * inv * qw[lane]);
        dst[lane + 32] = __float2bfloat16(v1 * inv * qw[lane + 32]);
        if (lane < 8)
            dst[lane + 64] = __float2bfloat16(v2 * inv * qw[lane + 64]);
    } else {
        const int rid = (blockIdx.x - QB) * 8 + wid;
        const int b = rid / (MKV * NH);
        const int m = (rid / NH) % MKV;
        const int h = rid % NH;

        const size_t base = ((size_t)(b * MKV + m) * 2) * DIM + h * HD;
        const float* ksrc = kv32 + base;
        const float* vsrc = kv32 + base + DIM;
        const float* kb   = kvb + h * HD;
        const float* vb   = kvb + DIM + h * HD;
        const size_t obase = ((size_t)(b * NH + h) * MKV + m) * HD;

        float k0 = ksrc[lane]      + kb[lane];
        float k1 = ksrc[lane + 32] + kb[lane + 32];
        float k2 = (lane < 8) ? ksrc[lane + 64] + kb[lane + 64] : 0.0f;
        float ss = k0 * k0 + k1 * k1 + k2 * k2;
        #pragma unroll
        for (int o = 16; o; o >>= 1) ss += __shfl_xor_sync(0xffffffffu, ss, o);
        const float inv = 1.0f / sqrtf(ss * (1.0f / 72.0f) + 1e-6f);
        k16[obase + lane]      = __float2bfloat16(k0 * inv * knw[lane]);
        k16[obase + lane + 32] = __float2bfloat16(k1 * inv * knw[lane + 32]);
        if (lane < 8)
            k16[obase + lane + 64] = __float2bfloat16(k2 * inv * knw[lane + 64]);

        v16[obase + lane]      = __float2bfloat16(vsrc[lane]      + vb[lane]);
        v16[obase + lane + 32] = __float2bfloat16(vsrc[lane + 32] + vb[lane + 32]);
        if (lane < 8)
            v16[obase + lane + 64] = __float2bfloat16(vsrc[lane + 64] + vb[lane + 64]);
    }
}

// ============================================================================
// Two-pass attention with FIXED softmax shift M=9 (|s·scale| provably < 9).
// Pass A: sum-only (no max scan, no rescale). Pass B: probs + PV.
// QT=64, ~69KB smem -> 3 blocks/SM, aliased prob buffer, __expf.
// ============================================================================
#define SCLD 132
#define PBLD 136
#define OFF_QS  0
#define OFF_KS  (OFF_QS + QT*HDP*2)            // 10240
#define OFF_SC  (OFF_KS + 128*HDV*2)           // 34816
#define OFF_S   (OFF_SC + QT*SCLD*4)           // 68608
#define SMEM_ATTN2 (OFF_S + QT*4)              // 68864

__global__ void __launch_bounds__(256, 3) attn_flash(
    const __nv_bfloat16* __restrict__ q16, const __nv_bfloat16* __restrict__ k16,
    const __nv_bfloat16* __restrict__ v16, const int* __restrict__ kvlen_p,
    __nv_bfloat16* __restrict__ out)
{
    extern __shared__ char smem[];
    __nv_bfloat16* qs  = (__nv_bfloat16*)(smem + OFF_QS);
    __nv_bfloat16* ks  = (__nv_bfloat16*)(smem + OFF_KS);
    float*         sc  = (float*)(smem + OFF_SC);
    __nv_bfloat16* pb  = (__nv_bfloat16*)(smem + OFF_SC);   // ALIASED
    float*         rowS = (float*)(smem + OFF_S);

    const int tid  = threadIdx.x;
    const int wid  = tid >> 5;
    const int lane = tid & 31;
    const int n0 = blockIdx.x * QT;
    const int h  = blockIdx.y;
    const int b  = blockIdx.z;
    const int kvlen = kvlen_p[b];
    const int nchunks = (kvlen + 127) >> 7;
    const float scale = 0.11785113019775793f;

    const size_t qbase = (((size_t)(b * NQ + n0)) * NH + h) * HD;
    for (int i = tid; i < QT * HDP; i += 256) {
        int r = i / HDP, c = i % HDP;
        qs[i] = (c < HD) ? q16[qbase + (size_t)r * NH * HD + c] : __float2bfloat16(0.0f);
    }
    if (tid < QT) rowS[tid] = 0.0f;

    const size_t kvbase = ((size_t)(b * NH + h)) * MKV * HD;
    const int rt = wid >> 1;
    const int ch = wid & 1;

    // Pass A: exp-sums (fixed shift, no max pass)
    for (int mc = 0; mc < nchunks; ++mc) {
        __syncthreads();
        for (int i = tid; i < 128 * HDP; i += 256) {
            int r = i / HDP, c = i % HDP;
            ks[r * HDP + c] = (c < HD)
                ? k16[kvbase + (size_t)(mc * 128 + r) * HD + c]
                : __float2bfloat16(0.0f);
        }
        __syncthreads();
        {
            wmma::fragment<wmma::matrix_a, 16, 16, 16, __nv_bfloat16, wmma::row_major> af;
            wmma::fragment<wmma::matrix_b, 16, 16, 16, __nv_bfloat16, wmma::col_major> bf;
            #pragma unroll
            for (int cc = 0; cc < 4; ++cc) {
                const int ct = ch * 4 + cc;
                wmma::fragment<wmma::accumulator, 16, 16, 16, float> acc;
                wmma::fill_fragment(acc, 0.0f);
                #pragma unroll
                for (int kk = 0; kk < 5; ++kk) {
                    wmma::load_matrix_sync(af, qs + rt * 16 * HDP + kk * 16, HDP);
                    wmma::load_matrix_sync(bf, ks + ct * 16 * HDP + kk * 16, HDP);
                    wmma::mma_sync(acc, af, bf, acc);
                }
                wmma::store_matrix_sync(sc + rt * 16 * SCLD + ct * 16, acc,
                                        SCLD, wmma::mem_row_major);
            }
        }
        __syncthreads();
        const int vmax = min(128, kvlen - mc * 128);
        for (int i = wid; i < QT; i += 8) {
            const float* row = sc + i * SCLD;
            float csum = 0.0f;
            for (int j = lane; j < vmax; j += 32)
                csum += __expf(row[j] * scale - MFIX);
            #pragma unroll
            for (int o = 16; o; o >>= 1)
                csum += __shfl_xor_sync(0xffffffffu, csum, o);
            if (lane == 0) rowS[i] += csum;
        }
    }
    __syncthreads();

    // Pass B: probs + PV
    wmma::fragment<wmma::accumulator, 16, 16, 16, float> pv[3];
    #pragma unroll
    for (int c3 = 0; c3 < 3; ++c3)
        wmma::fill_fragment(pv[c3], 0.0f);

    for (int mc = 0; mc < nchunks; ++mc) {
        for (int i = tid; i < 128 * HDP; i += 256) {
            int r = i / HDP, c = i % HDP;
            ks[r * HDP + c] = (c < HD)
                ? k16[kvbase + (size_t)(mc * 128 + r) * HD + c]
                : __float2bfloat16(0.0f);
        }
        __syncthreads();
        {
            wmma::fragment<wmma::matrix_a, 16, 16, 16, __nv_bfloat16, wmma::row_major> af;
            wmma::fragment<wmma::matrix_b, 16, 16, 16, __nv_bfloat16, wmma::col_major> bf;
            #pragma unroll
            for (int cc = 0; cc < 4; ++cc) {
                const int ct = ch * 4 + cc;
                wmma::fragment<wmma::accumulator, 16, 16, 16, float> acc;
                wmma::fill_fragment(acc, 0.0f);
                #pragma unroll
                for (int kk = 0; kk < 5; ++kk) {
                    wmma::load_matrix_sync(af, qs + rt * 16 * HDP + kk * 16, HDP);
                    wmma::load_matrix_sync(bf, ks + ct * 16 * HDP + kk * 16, HDP);
                    wmma::mma_sync(acc, af, bf, acc);
                }
                wmma::store_matrix_sync(sc + rt * 16 * SCLD + ct * 16, acc,
                                        SCLD, wmma::mem_row_major);
            }
        }
        __syncthreads();
        const int vmax = min(128, kvlen - mc * 128);
        float preg[8][4];
        #pragma unroll
        for (int t = 0; t < 8; ++t) {
            const int i = wid + 8 * t;
            const float invS = 1.0f / rowS[i];
            const float* row = sc + i * SCLD;
            #pragma unroll
            for (int q = 0; q < 4; ++q) {
                const int j = lane + 32 * q;
                preg[t][q] = (j < vmax)
                    ? __expf(row[j] * scale - MFIX) * invS : 0.0f;
            }
        }
        __syncthreads();
        #pragma unroll
        for (int t = 0; t < 8; ++t) {
            const int i = wid + 8 * t;
            __nv_bfloat16* prow = pb + i * PBLD;
            #pragma unroll
            for (int q = 0; q < 4; ++q)
                prow[lane + 32 * q] = __float2bfloat16(preg[t][q]);
        }
        for (int i = tid; i < 128 * HDV; i += 256) {
            int r = i / HDV, c = i % HDV;
            ks[r * HDV + c] = (c < HD)
                ? v16[kvbase + (size_t)(mc * 128 + r) * HD + c]
                : __float2bfloat16(0.0f);
        }
        __syncthreads();
        {
            wmma::fragment<wmma::matrix_a, 16, 16, 16, __nv_bfloat16, wmma::row_major> pf;
            wmma::fragment<wmma::matrix_b, 16, 16, 16, __nv_bfloat16, wmma::row_major> vf;
            #pragma unroll
            for (int kk = 0; kk < 8; ++kk) {
                wmma::load_matrix_sync(pf, pb + rt * 16 * PBLD + kk * 16, PBLD);
                #pragma unroll
                for (int c3 = 0; c3 < 3; ++c3) {
                    wmma::load_matrix_sync(vf, ks + kk * 16 * HDV + (ch * 3 + c3) * 16, HDV);
                    wmma::mma_sync(pv[c3], pf, vf, pv[c3]);
                }
            }
        }
        __syncthreads();
    }

    float* os = sc;
    #pragma unroll
    for (int c3 = 0; c3 < 3; ++c3)
        wmma::store_matrix_sync(os + rt * 16 * HDV + (ch * 3 + c3) * 16, pv[c3],
                                HDV, wmma::mem_row_major);
    __syncthreads();
    for (int i = tid; i < QT * HD; i += 256) {
        int r = i / HD, d = i % HD;
        out[((size_t)(b * NQ + n0 + r)) * DIM + h * HD + d] =
            __float2bfloat16(os[r * HDV + d]);
    }
}

// ============================================================================
extern "C" void kernel_launch(void* const* d_in, const int* in_sizes, int n_in,
                              void* d_out, int out_size)
{
    (void)in_sizes; (void)n_in; (void)out_size;
    const float* x      = (const float*)d_in[0];
    const float* cond   = (const float*)d_in[1];
    const int*   kvlen  = (const int*)  d_in[2];
    const float* q_w    = (const float*)d_in[3];
    const float* q_b    = (const float*)d_in[4];
    const float* kv_w   = (const float*)d_in[5];
    const float* kv_b   = (const float*)d_in[6];
    const float* proj_w = (const float*)d_in[7];
    const float* proj_b = (const float*)d_in[8];
    const float* qn_w   = (const float*)d_in[9];
    const float* kn_w   = (const float*)d_in[10];
    float* out = (float*)d_out;

    void* p;
    cudaGetSymbolAddress(&p, g_q32);   float* q32 = (float*)p;
    cudaGetSymbolAddress(&p, g_kv32);  float* kv32 = (float*)p;
    cudaGetSymbolAddress(&p, g_q16);   __nv_bfloat16* q16 = (__nv_bfloat16*)p;
    cudaGetSymbolAddress(&p, g_k16);   __nv_bfloat16* k16 = (__nv_bfloat16*)p;
    cudaGetSymbolAddress(&p, g_v16);   __nv_bfloat16* v16 = (__nv_bfloat16*)p;
    cudaGetSymbolAddress(&p, g_att16); __nv_bfloat16* att16 = (__nv_bfloat16*)p;
    cudaGetSymbolAddress(&p, g_pwh);   __nv_bfloat16* pwh = (__nv_bfloat16*)p;
    cudaGetSymbolAddress(&p, g_pwl);   __nv_bfloat16* pwl = (__nv_bfloat16*)p;

    cudaFuncSetAttribute(attn_flash, cudaFuncAttributeMaxDynamicSharedMemorySize,
                         SMEM_ATTN2);

    // 0) Q-proj + KV-proj in one launch (exact fp32)
    gemm_dual_f32<<<QBLK + KVBLK, 256>>>(x, q_w, q32, cond, kv_w, kv32);
    // 0b) pre-split proj_w (overlaps with nothing it depends on)
    split_w_kernel<<<(DIM * DIM) / 1024, 256>>>(proj_w, pwh, pwl);
    // 1) fused bias + rmsnorm + bf16
    rms_fused<<<QB + KB, 256>>>(q32, q_b, qn_w, q16, kv32, kv_b, kn_w, k16, v16);
    // 2) attention — fixed-shift two-pass
    attn_flash<<<dim3(NQ / QT, NH, BB), 256, SMEM_ATTN2>>>(q16, k16, v16, kvlen, att16);
    // 3) out = att @ proj_w + proj_b — bf16x2 tensor-core, pre-split B
    gemm_out_bf16<<<dim3(DIM / 128, (BB * NQ) / 128), 256>>>(
        att16, pwh, pwl, proj_b, out, BB * NQ, DIM, DIM);
}